// round 1
// baseline (speedup 1.0000x reference)
#include <cuda_runtime.h>

// ---------------- problem constants ----------------
static constexpr int BB   = 256;   // batch
static constexpr int HH   = 128;   // hidden
static constexpr int INP  = 128;   // input dim
static constexpr int GD   = 384;   // gate input dim = INP + 2H
static constexpr int NG   = 5;     // gates
static constexpr int NOUT = 640;   // NG * HH
static constexpr int NTREE = 1023; // nodes in tree
static constexpr int MAXLEVEL_N = 512;       // nodes at level d=9
static constexpr int MAXR = BB * MAXLEVEL_N; // 131072 rows max

// ---------------- static device scratch (no allocations allowed) ----------------
__device__ float g_h[2][(size_t)BB * MAXLEVEL_N * HH];   // 2 x 67MB
__device__ float g_c[2][(size_t)BB * MAXLEVEL_N * HH];   // 2 x 67MB
__device__ float g_comb[(size_t)MAXR * GD];              // 201MB
__device__ float g_pre[(size_t)MAXR * NOUT];             // 335MB
__device__ float g_Wp[NOUT * GD];                        // packed weights [640 x 384]
__device__ float g_bp[NOUT];

// ---------------- pack 5 gate weight matrices into one [640 x 384] ----------------
__global__ void pack_w(const float* __restrict__ Wi, const float* __restrict__ bi,
                       const float* __restrict__ Wfl, const float* __restrict__ bfl,
                       const float* __restrict__ Wfr, const float* __restrict__ bfr,
                       const float* __restrict__ Wo, const float* __restrict__ bo,
                       const float* __restrict__ Wu, const float* __restrict__ bu) {
    const float* Ws[NG] = {Wi, Wfl, Wfr, Wo, Wu};
    const float* bs[NG] = {bi, bfl, bfr, bo, bu};
    int idx = blockIdx.x * blockDim.x + threadIdx.x;
    if (idx < NOUT * GD) {
        int row = idx / GD, k = idx % GD;
        int g = row >> 7, o = row & 127;
        g_Wp[idx] = Ws[g][o * GD + k];
    }
    if (idx < NOUT) {
        int g = idx >> 7, o = idx & 127;
        g_bp[idx] = bs[g][o];
    }
}

// ---------------- gather comb = [x_slice | h_left | h_right] ----------------
// one thread per float4 of comb
__global__ void build_comb(const float* __restrict__ x, int n, int parity_prev, int has_children) {
    int idx = blockIdx.x * blockDim.x + threadIdx.x;
    int R = BB * n;
    if (idx >= R * 96) return;          // 96 float4 per row (384 floats)
    int r = idx / 96;
    int q = idx % 96;
    int b = r / n, j = r % n;
    float4 v;
    if (q < 32) {
        // x[b, (n-1)+j, :]
        v = reinterpret_cast<const float4*>(x)[((size_t)b * NTREE + (n - 1 + j)) * 32 + q];
    } else if (!has_children) {
        v = make_float4(0.f, 0.f, 0.f, 0.f);
    } else if (q < 64) {
        v = reinterpret_cast<const float4*>(g_h[parity_prev])[((size_t)b * (2 * n) + 2 * j) * 32 + (q - 32)];
    } else {
        v = reinterpret_cast<const float4*>(g_h[parity_prev])[((size_t)b * (2 * n) + 2 * j + 1) * 32 + (q - 64)];
    }
    reinterpret_cast<float4*>(g_comb)[(size_t)r * 96 + q] = v;
}

// ---------------- fused-bias SGEMM: pre[M x 640] = comb[M x 384] @ Wp^T + bp ----------------
// BM=128, BN=128, BK=16, 256 threads, 8x8 micro-tile per thread.
// M is always a multiple of 256, N = 640 = 5*128, K = 384 = 24*16 -> no bounds checks.
__global__ void __launch_bounds__(256) gemm_pre(int M) {
    __shared__ float As[16][128];  // transposed: As[k][m]
    __shared__ float Bs[16][128];  // transposed: Bs[k][n]
    const int bm = blockIdx.x * 128;
    const int bn = blockIdx.y * 128;
    const int tid = threadIdx.x;
    const int tm = tid >> 4;       // 0..15
    const int tn = tid & 15;       // 0..15

    float acc[8][8];
    #pragma unroll
    for (int i = 0; i < 8; i++)
        #pragma unroll
        for (int j = 0; j < 8; j++) acc[i][j] = 0.f;

    for (int k0 = 0; k0 < GD; k0 += 16) {
        // load A tile (128 rows x 16 k) and B tile, store transposed
        #pragma unroll
        for (int l = 0; l < 2; l++) {
            int f = tid + l * 256;        // 0..511
            int row = f >> 2;             // 0..127
            int c4  = f & 3;              // which float4 within the 16 k's
            float4 va = reinterpret_cast<const float4*>(g_comb)[(((size_t)(bm + row)) * GD + k0) / 4 + c4];
            As[c4 * 4 + 0][row] = va.x;
            As[c4 * 4 + 1][row] = va.y;
            As[c4 * 4 + 2][row] = va.z;
            As[c4 * 4 + 3][row] = va.w;
            float4 vb = reinterpret_cast<const float4*>(g_Wp)[(((size_t)(bn + row)) * GD + k0) / 4 + c4];
            Bs[c4 * 4 + 0][row] = vb.x;
            Bs[c4 * 4 + 1][row] = vb.y;
            Bs[c4 * 4 + 2][row] = vb.z;
            Bs[c4 * 4 + 3][row] = vb.w;
        }
        __syncthreads();

        #pragma unroll
        for (int kk = 0; kk < 16; kk++) {
            float a[8], b[8];
            *reinterpret_cast<float4*>(&a[0]) = *reinterpret_cast<const float4*>(&As[kk][tm * 8]);
            *reinterpret_cast<float4*>(&a[4]) = *reinterpret_cast<const float4*>(&As[kk][tm * 8 + 4]);
            *reinterpret_cast<float4*>(&b[0]) = *reinterpret_cast<const float4*>(&Bs[kk][tn * 8]);
            *reinterpret_cast<float4*>(&b[4]) = *reinterpret_cast<const float4*>(&Bs[kk][tn * 8 + 4]);
            #pragma unroll
            for (int i = 0; i < 8; i++)
                #pragma unroll
                for (int j = 0; j < 8; j++) acc[i][j] += a[i] * b[j];
        }
        __syncthreads();
    }

    // epilogue: add bias, store
    #pragma unroll
    for (int i = 0; i < 8; i++) {
        int m = bm + tm * 8 + i;
        #pragma unroll
        for (int j = 0; j < 8; j += 4) {
            int nn = bn + tn * 8 + j;
            float4 o;
            o.x = acc[i][j + 0] + g_bp[nn + 0];
            o.y = acc[i][j + 1] + g_bp[nn + 1];
            o.z = acc[i][j + 2] + g_bp[nn + 2];
            o.w = acc[i][j + 3] + g_bp[nn + 3];
            reinterpret_cast<float4*>(g_pre)[((size_t)m * NOUT + nn) / 4] = o;
        }
    }
}

// ---------------- gate activations + cell/hidden update ----------------
__device__ __forceinline__ float sigf(float v) { return 1.f / (1.f + __expf(-v)); }

__global__ void combine(int n, int parity, int parity_prev, int has_children) {
    int idx = blockIdx.x * blockDim.x + threadIdx.x;
    int R = BB * n;
    if (idx >= R * 32) return;   // 32 float4 per row of H
    int r = idx / 32;
    int q = idx % 32;
    int b = r / n, j = r % n;

    const float4* pre = reinterpret_cast<const float4*>(g_pre);
    size_t base = (size_t)r * 160;  // 640/4
    float4 pi  = pre[base + 0 * 32 + q];
    float4 pfl = pre[base + 1 * 32 + q];
    float4 pfr = pre[base + 2 * 32 + q];
    float4 po  = pre[base + 3 * 32 + q];
    float4 pu  = pre[base + 4 * 32 + q];

    float4 cl = make_float4(0.f, 0.f, 0.f, 0.f);
    float4 cr = cl;
    if (has_children) {
        const float4* cprev = reinterpret_cast<const float4*>(g_c[parity_prev]);
        cl = cprev[((size_t)b * (2 * n) + 2 * j) * 32 + q];
        cr = cprev[((size_t)b * (2 * n) + 2 * j + 1) * 32 + q];
    }

    float4 co, ho;
    {
        float cc = sigf(pi.x) * tanhf(pu.x) + sigf(pfl.x) * cl.x + sigf(pfr.x) * cr.x;
        co.x = cc; ho.x = sigf(po.x) * tanhf(cc);
    }
    {
        float cc = sigf(pi.y) * tanhf(pu.y) + sigf(pfl.y) * cl.y + sigf(pfr.y) * cr.y;
        co.y = cc; ho.y = sigf(po.y) * tanhf(cc);
    }
    {
        float cc = sigf(pi.z) * tanhf(pu.z) + sigf(pfl.z) * cl.z + sigf(pfr.z) * cr.z;
        co.z = cc; ho.z = sigf(po.z) * tanhf(cc);
    }
    {
        float cc = sigf(pi.w) * tanhf(pu.w) + sigf(pfl.w) * cl.w + sigf(pfr.w) * cr.w;
        co.w = cc; ho.w = sigf(po.w) * tanhf(cc);
    }

    reinterpret_cast<float4*>(g_c[parity])[(size_t)r * 32 + q] = co;
    reinterpret_cast<float4*>(g_h[parity])[(size_t)r * 32 + q] = ho;
}

// ---------------- final classifier: logits = h_root @ W_cls^T + b_cls ----------------
__global__ void cls_kernel(const float* __restrict__ Wc, const float* __restrict__ bc,
                           float* __restrict__ out) {
    int idx = blockIdx.x * blockDim.x + threadIdx.x;   // B*C = 1280
    if (idx >= BB * 5) return;
    int b = idx / 5, cc = idx % 5;
    const float* hr = g_h[0] + (size_t)b * HH;         // root (d=0) lives at parity 0
    float s = bc[cc];
    #pragma unroll 4
    for (int h = 0; h < HH; h++) s += hr[h] * Wc[cc * HH + h];
    out[idx] = s;
}

// ---------------- launch ----------------
extern "C" void kernel_launch(void* const* d_in, const int* in_sizes, int n_in,
                              void* d_out, int out_size) {
    (void)in_sizes; (void)n_in; (void)out_size;
    const float* x = (const float*)d_in[0];

    pack_w<<<(NOUT * GD + 255) / 256, 256>>>(
        (const float*)d_in[1], (const float*)d_in[2],
        (const float*)d_in[3], (const float*)d_in[4],
        (const float*)d_in[5], (const float*)d_in[6],
        (const float*)d_in[7], (const float*)d_in[8],
        (const float*)d_in[9], (const float*)d_in[10]);

    for (int d = 9; d >= 0; d--) {
        int n = 1 << d;
        int R = BB * n;
        int has = (d == 9) ? 0 : 1;
        int pp = (d + 1) & 1;   // parity of children level
        int p  = d & 1;         // parity of this level

        build_comb<<<(R * 96 + 255) / 256, 256>>>(x, n, pp, has);

        dim3 grid(R / 128, NOUT / 128);
        gemm_pre<<<grid, 256>>>(R);

        combine<<<(R * 32 + 255) / 256, 256>>>(n, p, pp, has);
    }

    cls_kernel<<<(BB * 5 + 127) / 128, 128>>>(
        (const float*)d_in[11], (const float*)d_in[12], (float*)d_out);
}

// round 3
// speedup vs baseline: 2.2770x; 2.2770x over previous
#include <cuda_runtime.h>
#include <cuda_bf16.h>
#include <cstdint>

#define DI __device__ __forceinline__

static constexpr int BB   = 256;
static constexpr int HH   = 128;
static constexpr int GD   = 384;
static constexpr int NTREE= 1023;
static constexpr int KW   = 768;     // comb row: [hi(384) | lo(384)] bf16
static constexpr int KBIG = 1152;    // virtual K = 3 * 384 (split-bf16 3-pass)
static constexpr int NCH  = 18;      // K chunks of 64
static constexpr int MAXR = 131072;

// ---------------- static device scratch ----------------
__device__ __nv_bfloat16 g_comb[(size_t)MAXR * KW];   // 201MB
__device__ __nv_bfloat16 g_Wb[640 * KBIG];            // packed weights
__device__ float g_bpk[640];
__device__ float g_cst[2][(size_t)MAXR * HH];         // cell state ping-pong
__device__ float g_root[BB * HH];

// ---------------- helpers ----------------
DI uint32_t smem_u32(const void* p){ uint32_t a;
  asm("{ .reg .u64 t; cvta.to.shared.u64 t, %1; cvt.u32.u64 %0, t; }":"=r"(a):"l"(p)); return a; }
DI uint32_t swz(uint32_t o){ return o ^ ((o >> 3) & 0x70); }
DI void cp16(uint32_t dst, const void* src){
  asm volatile("cp.async.cg.shared.global [%0], [%1], 16;"
               ::"r"(dst),"l"(__cvta_generic_to_global(src)):"memory"); }
DI float sigf(float v){ return 1.f/(1.f+__expf(-v)); }
DI uint32_t lds32(uint32_t a){ uint32_t v;
  asm volatile("ld.shared.b32 %0, [%1];":"=r"(v):"r"(a)); return v; }
DI void ldsm4(uint32_t* a, uint32_t addr){
  asm volatile("ldmatrix.sync.aligned.m8n8.x4.shared.b16 {%0,%1,%2,%3}, [%4];"
    : "=r"(a[0]),"=r"(a[1]),"=r"(a[2]),"=r"(a[3]) : "r"(addr)); }
DI void hmma(float* d, const uint32_t* a, const uint32_t* b){
  asm volatile("mma.sync.aligned.m16n8k16.row.col.f32.bf16.bf16.f32 "
    "{%0,%1,%2,%3}, {%4,%5,%6,%7}, {%8,%9}, {%0,%1,%2,%3};"
    : "+f"(d[0]),"+f"(d[1]),"+f"(d[2]),"+f"(d[3])
    : "r"(a[0]),"r"(a[1]),"r"(a[2]),"r"(a[3]), "r"(b[0]),"r"(b[1])); }

// ---------------- pack weights ----------------
// packed n = (h>>3)*40 + g*8 + (h&7)  -> each 40-col slice = 5 gates x 8 h
// K layout = [hi | hi | lo] of the 384 true K
__global__ void pack_w(const float* __restrict__ Wi, const float* __restrict__ bi,
                       const float* __restrict__ Wfl,const float* __restrict__ bfl,
                       const float* __restrict__ Wfr,const float* __restrict__ bfr,
                       const float* __restrict__ Wo, const float* __restrict__ bo,
                       const float* __restrict__ Wu, const float* __restrict__ bu) {
    const float* Ws[5] = {Wi, Wfl, Wfr, Wo, Wu};
    const float* bs[5] = {bi, bfl, bfr, bo, bu};
    int idx = blockIdx.x * blockDim.x + threadIdx.x;
    if (idx < 640 * KBIG) {
        int nn = idx / KBIG, k = idx % KBIG;
        int p = k / GD, kp = k % GD;
        int hoct = nn / 40, rem = nn % 40, g = rem / 8, h3 = rem % 8;
        int h = hoct * 8 + h3;
        float w = Ws[g][h * GD + kp];
        __nv_bfloat16 hi = __float2bfloat16(w);
        g_Wb[idx] = (p < 2) ? hi : __float2bfloat16(w - __bfloat162float(hi));
    }
    if (idx < 640) {
        int hoct = idx / 40, rem = idx % 40, g = rem / 8, h3 = rem % 8;
        g_bpk[idx] = bs[g][hoct * 8 + h3];
    }
}

// ---------------- build x part of comb (bf16 hi/lo) ----------------
__global__ void build_x(const float* __restrict__ x, int n, int leaf) {
    int idx = blockIdx.x * blockDim.x + threadIdx.x;
    int R = BB * n;
    if (idx >= R * 32) return;
    int r = idx >> 5, q = idx & 31;
    int b = r / n, j = r % n;
    float4 v = reinterpret_cast<const float4*>(x)[((size_t)b * NTREE + (n - 1 + j)) * 32 + q];
    __nv_bfloat16 hb[4], lb[4];
    float vv[4] = {v.x, v.y, v.z, v.w};
    #pragma unroll
    for (int t = 0; t < 4; t++) {
        hb[t] = __float2bfloat16(vv[t]);
        lb[t] = __float2bfloat16(vv[t] - __bfloat162float(hb[t]));
    }
    __nv_bfloat16* row = g_comb + (size_t)r * KW;
    *reinterpret_cast<uint2*>(row + q * 4)       = *reinterpret_cast<uint2*>(hb);
    *reinterpret_cast<uint2*>(row + 384 + q * 4) = *reinterpret_cast<uint2*>(lb);
    if (leaf) {
        uint4 z = make_uint4(0, 0, 0, 0);
        *reinterpret_cast<uint4*>(row + 128 + q * 8) = z;
        *reinterpret_cast<uint4*>(row + 512 + q * 8) = z;
    }
}

// ---------------- fused GEMM (mma.sync bf16) + LSTM epilogue ----------------
// CTA: MT rows x 160 cols (4 h-octets x 5 gates x 8 h), K = 1152
// 8 warps: warpM = wid>>2 (2 groups of MT/2 rows), warpN = wid&3 (one 40-col slice)
template<int MT>
__global__ void __launch_bounds__(256, 1) gemm_fused(
    int n, int log2n, int parity, int parity_prev, int has_children, int is_root)
{
    constexpr int MF = MT / 32;                    // m16 frags per warp
    constexpr uint32_t STAGE_A = (uint32_t)MT * 128;
    constexpr uint32_t STAGE   = STAGE_A + 20480;  // + B: 160 rows x 128B
    extern __shared__ char smem[];
    const uint32_t sb = smem_u32(smem);
    const int tid = threadIdx.x, wid = tid >> 5, lane = tid & 31;
    const int blkh = blockIdx.x;                   // h block of 32 (0..3)
    const int bm   = blockIdx.y * MT;
    const int warpM = wid >> 2, warpN = wid & 3;

    float* sbias = reinterpret_cast<float*>(smem);
    if (tid < 160) sbias[tid] = g_bpk[blkh * 160 + tid];

    float acc[MF][5][4];
    #pragma unroll
    for (int a = 0; a < MF; a++)
      #pragma unroll
      for (int b = 0; b < 5; b++)
        #pragma unroll
        for (int c = 0; c < 4; c++) acc[a][b][c] = 0.f;

    auto load_chunk = [&](int ch) {
        const uint32_t base = sb + 1024 + (uint32_t)(ch & 1) * STAGE;
        const int p = ch / 6, kk = (ch % 6) * 64;
        const int acol = (p == 1) ? 384 + kk : kk;     // A' = [hi, lo, hi]
        const __nv_bfloat16* abase = g_comb + (size_t)bm * KW + acol;
        #pragma unroll
        for (int l = 0; l < MT / 32; l++) {
            int t = tid + l * 256; int row = t >> 3, c = t & 7;
            cp16(base + swz(row * 128 + c * 16),
                 reinterpret_cast<const char*>(abase + (size_t)row * KW) + c * 16);
        }
        const __nv_bfloat16* bbase = g_Wb + (size_t)(blkh * 160) * KBIG + ch * 64;
        #pragma unroll
        for (int l = 0; l < 5; l++) {
            int t = tid + l * 256; int row = t >> 3, c = t & 7;
            cp16(base + STAGE_A + swz(row * 128 + c * 16),
                 reinterpret_cast<const char*>(bbase + (size_t)row * KBIG) + c * 16);
        }
        asm volatile("cp.async.commit_group;" ::: "memory");
    };

    load_chunk(0); load_chunk(1);

    // per-thread fragment addressing
    const int mat = lane >> 3, r8 = lane & 7;
    const int a_row = warpM * (MT / 2) + (mat & 1) * 8 + r8;   // + mi*16
    const int a_kb  = (mat >> 1) * 16;                          // + kk*32
    const int b_row = warpN * 40 + (lane >> 2);                 // + j*8
    const int b_kb  = (lane & 3) * 4;                           // + kk*32

    for (int i = 0; i < NCH; i++) {
        if (i == NCH - 1) asm volatile("cp.async.wait_group 0;" ::: "memory");
        else              asm volatile("cp.async.wait_group 1;" ::: "memory");
        __syncthreads();
        const uint32_t base = sb + 1024 + (uint32_t)(i & 1) * STAGE;
        #pragma unroll
        for (int kk = 0; kk < 4; kk++) {
            uint32_t bf[5][2];
            #pragma unroll
            for (int j = 0; j < 5; j++) {
                uint32_t o = (uint32_t)((b_row + j * 8) * 128 + kk * 32 + b_kb);
                bf[j][0] = lds32(base + STAGE_A + swz(o));
                bf[j][1] = lds32(base + STAGE_A + swz(o + 16));
            }
            #pragma unroll
            for (int mi = 0; mi < MF; mi++) {
                uint32_t a[4];
                uint32_t o = (uint32_t)((a_row + mi * 16) * 128 + kk * 32 + a_kb);
                ldsm4(a, base + swz(o));
                #pragma unroll
                for (int j = 0; j < 5; j++) hmma(acc[mi][j], a, bf[j]);
            }
        }
        __syncthreads();
        if (i + 2 < NCH) load_chunk(i + 2);
    }

    // ---- fused epilogue: all 5 gates for (r,h) live in this thread ----
    const float* cprev = g_cst[parity_prev];
    float* cout = g_cst[parity];
    const int hbase = blkh * 32 + warpN * 8;
    const int nl = warpN * 40;
    #pragma unroll
    for (int mi = 0; mi < MF; mi++) {
        #pragma unroll
        for (int c = 0; c < 4; c++) {
            int r = bm + warpM * (MT / 2) + mi * 16 + (lane >> 2) + ((c & 2) ? 8 : 0);
            int hsub = (lane & 3) * 2 + (c & 1);
            int h = hbase + hsub;
            float vi  = sigf(acc[mi][0][c] + sbias[nl +  0 + hsub]);
            float vfl = sigf(acc[mi][1][c] + sbias[nl +  8 + hsub]);
            float vfr = sigf(acc[mi][2][c] + sbias[nl + 16 + hsub]);
            float vo  = sigf(acc[mi][3][c] + sbias[nl + 24 + hsub]);
            float vu  = tanhf(acc[mi][4][c] + sbias[nl + 32 + hsub]);
            int b_ = r >> log2n, j_ = r & (n - 1);
            float cl = 0.f, cr = 0.f;
            if (has_children) {
                size_t chL = ((size_t)b_ * (2 * n) + 2 * j_) * HH;
                cl = cprev[chL + h];
                cr = cprev[chL + HH + h];
            }
            float cc = vi * vu + vfl * cl + vfr * cr;
            float hh = vo * tanhf(cc);
            cout[(size_t)r * HH + h] = cc;
            if (is_root) {
                g_root[r * HH + h] = hh;
            } else {
                __nv_bfloat16 hi = __float2bfloat16(hh);
                __nv_bfloat16 lo = __float2bfloat16(hh - __bfloat162float(hi));
                __nv_bfloat16* pc = g_comb + ((size_t)b_ * (n >> 1) + (j_ >> 1)) * KW
                                    + 128 + (j_ & 1) * 128;
                pc[h] = hi;
                pc[384 + h] = lo;
            }
        }
    }
}

// ---------------- final classifier ----------------
__global__ void cls_kernel(const float* __restrict__ Wc, const float* __restrict__ bc,
                           float* __restrict__ out) {
    int idx = blockIdx.x * blockDim.x + threadIdx.x;
    if (idx >= BB * 5) return;
    int b = idx / 5, cc = idx % 5;
    const float* hr = g_root + (size_t)b * HH;
    float s = bc[cc];
    #pragma unroll 4
    for (int h = 0; h < HH; h++) s += hr[h] * Wc[cc * HH + h];
    out[idx] = s;
}

// ---------------- launch ----------------
extern "C" void kernel_launch(void* const* d_in, const int* in_sizes, int n_in,
                              void* d_out, int out_size) {
    (void)in_sizes; (void)n_in; (void)out_size;
    const float* x = (const float*)d_in[0];

    constexpr int SMEM256 = 1024 + 2 * (256 * 128 + 20480);  // 107520
    constexpr int SMEM128 = 1024 + 2 * (128 * 128 + 20480);  // 74752
    cudaFuncSetAttribute(gemm_fused<256>, cudaFuncAttributeMaxDynamicSharedMemorySize, SMEM256);
    cudaFuncSetAttribute(gemm_fused<128>, cudaFuncAttributeMaxDynamicSharedMemorySize, SMEM128);

    pack_w<<<(640 * KBIG + 255) / 256, 256>>>(
        (const float*)d_in[1], (const float*)d_in[2],
        (const float*)d_in[3], (const float*)d_in[4],
        (const float*)d_in[5], (const float*)d_in[6],
        (const float*)d_in[7], (const float*)d_in[8],
        (const float*)d_in[9], (const float*)d_in[10]);

    for (int d = 9; d >= 0; d--) {
        int n = 1 << d;
        int R = BB * n;
        build_x<<<(R * 32 + 255) / 256, 256>>>(x, n, d == 9);
        if (d >= 7) {
            dim3 grid(4, R / 256);
            gemm_fused<256><<<grid, 256, SMEM256>>>(n, d, d & 1, (d + 1) & 1, d < 9, d == 0);
        } else {
            dim3 grid(4, R / 128);
            gemm_fused<128><<<grid, 256, SMEM128>>>(n, d, d & 1, (d + 1) & 1, d < 9, d == 0);
        }
    }

    cls_kernel<<<(BB * 5 + 127) / 128, 128>>>(
        (const float*)d_in[11], (const float*)d_in[12], (float*)d_out);
}